// round 2
// baseline (speedup 1.0000x reference)
#include <cuda_runtime.h>
#include <cstdint>
#include <cstddef>

#define T_SEQ   2048
#define D_DIM   256
#define B_BATCH 32
#define H_DIM   1024
#define M_ROWS  (B_BATCH * T_SEQ)          /* 65536 */
#define HALF_OFF ((size_t)M_ROWS * 256)    /* split point in d_out */

// Scratch (static device globals: allocation-free per harness rules)
__device__ float g_ctx[(size_t)M_ROWS * D_DIM];     // 64 MB
__device__ float g_h[(size_t)M_ROWS * H_DIM];       // 256 MB

// ---------------------------------------------------------------------------
// tf32 mma.sync helpers
// ---------------------------------------------------------------------------
__device__ __forceinline__ uint32_t f2tf(float f) {
    uint32_t u;
    asm("cvt.rna.tf32.f32 %0, %1;" : "=r"(u) : "f"(f));
    return u;
}

__device__ __forceinline__ void mma_tf32(float& c0, float& c1, float& c2, float& c3,
                                         uint32_t a0, uint32_t a1, uint32_t a2, uint32_t a3,
                                         uint32_t b0, uint32_t b1)
{
    asm volatile(
        "mma.sync.aligned.m16n8k8.row.col.f32.tf32.tf32.f32 "
        "{%0,%1,%2,%3},{%4,%5,%6,%7},{%8,%9},{%0,%1,%2,%3};\n"
        : "+f"(c0), "+f"(c1), "+f"(c2), "+f"(c3)
        : "r"(a0), "r"(a1), "r"(a2), "r"(a3), "r"(b0), "r"(b1));
}

// ---------------------------------------------------------------------------
// Attention: flash-style fp32 (unchanged from round 1 — converts next round)
// ---------------------------------------------------------------------------
#define QP 68
#define KP 261
#define PP 68
#define ATTN_SMEM ((256 * QP + 64 * KP + 64 * PP) * 4)

__global__ __launch_bounds__(256, 1)
void attn_kernel(const float* __restrict__ x)
{
    extern __shared__ float sm[];
    float* Qt = sm;                 // [256][QP]
    float* Ks = sm + 256 * QP;      // [64][KP]
    float* Ps = Ks + 64 * KP;       // [64][PP]

    const int qt  = blockIdx.x;
    const int b   = blockIdx.y;
    const int tid = threadIdx.x;
    const int tx  = tid & 15;
    const int ty  = tid >> 4;
    const float* xb = x + (size_t)b * T_SEQ * D_DIM;
    const int q0 = qt * 64;

    for (int idx = tid; idx < 64 * 64; idx += 256) {
        int ii = idx >> 6, d4 = idx & 63;
        float4 v = *(const float4*)(xb + (size_t)(q0 + ii) * D_DIM + d4 * 4);
        Qt[(d4 * 4 + 0) * QP + ii] = v.x * 0.0625f;
        Qt[(d4 * 4 + 1) * QP + ii] = v.y * 0.0625f;
        Qt[(d4 * 4 + 2) * QP + ii] = v.z * 0.0625f;
        Qt[(d4 * 4 + 3) * QP + ii] = v.w * 0.0625f;
    }

    float acc[4][16];
    #pragma unroll
    for (int r = 0; r < 4; r++)
        #pragma unroll
        for (int c = 0; c < 16; c++) acc[r][c] = 0.f;
    float mr[4], lr[4];
    #pragma unroll
    for (int r = 0; r < 4; r++) { mr[r] = -1e30f; lr[r] = 0.f; }

    for (int kt = 0; kt <= qt; ++kt) {
        __syncthreads();
        for (int idx = tid; idx < 64 * 64; idx += 256) {
            int jj = idx >> 6, d4 = idx & 63;
            float4 v = *(const float4*)(xb + (size_t)(kt * 64 + jj) * D_DIM + d4 * 4);
            float* kp = Ks + jj * KP + d4 * 4;
            kp[0] = v.x; kp[1] = v.y; kp[2] = v.z; kp[3] = v.w;
        }
        __syncthreads();

        float s[4][4];
        #pragma unroll
        for (int r = 0; r < 4; r++)
            #pragma unroll
            for (int jj = 0; jj < 4; jj++) s[r][jj] = 0.f;

        #pragma unroll 4
        for (int d = 0; d < 256; ++d) {
            float4 q = *(const float4*)&Qt[d * QP + ty * 4];
            #pragma unroll
            for (int jj = 0; jj < 4; jj++) {
                float kv = Ks[(tx + 16 * jj) * KP + d];
                s[0][jj] += q.x * kv;
                s[1][jj] += q.y * kv;
                s[2][jj] += q.z * kv;
                s[3][jj] += q.w * kv;
            }
        }

        if (kt == qt) {
            #pragma unroll
            for (int r = 0; r < 4; r++)
                #pragma unroll
                for (int jj = 0; jj < 4; jj++)
                    if (tx + 16 * jj >= ty * 4 + r) s[r][jj] = -1e30f;
        }

        #pragma unroll
        for (int r = 0; r < 4; r++) {
            float rm = fmaxf(fmaxf(s[r][0], s[r][1]), fmaxf(s[r][2], s[r][3]));
            rm = fmaxf(rm, __shfl_xor_sync(0xffffffffu, rm, 1, 16));
            rm = fmaxf(rm, __shfl_xor_sync(0xffffffffu, rm, 2, 16));
            rm = fmaxf(rm, __shfl_xor_sync(0xffffffffu, rm, 4, 16));
            rm = fmaxf(rm, __shfl_xor_sync(0xffffffffu, rm, 8, 16));
            float mn = fmaxf(mr[r], rm);
            float sc = __expf(mr[r] - mn);
            mr[r] = mn;
            float ps0 = __expf(s[r][0] - mn);
            float ps1 = __expf(s[r][1] - mn);
            float ps2 = __expf(s[r][2] - mn);
            float ps3 = __expf(s[r][3] - mn);
            float rs = ps0 + ps1 + ps2 + ps3;
            rs += __shfl_xor_sync(0xffffffffu, rs, 1, 16);
            rs += __shfl_xor_sync(0xffffffffu, rs, 2, 16);
            rs += __shfl_xor_sync(0xffffffffu, rs, 4, 16);
            rs += __shfl_xor_sync(0xffffffffu, rs, 8, 16);
            lr[r] = lr[r] * sc + rs;
            #pragma unroll
            for (int cc = 0; cc < 16; cc++) acc[r][cc] *= sc;
            Ps[(tx + 16 * 0) * PP + ty * 4 + r] = ps0;
            Ps[(tx + 16 * 1) * PP + ty * 4 + r] = ps1;
            Ps[(tx + 16 * 2) * PP + ty * 4 + r] = ps2;
            Ps[(tx + 16 * 3) * PP + ty * 4 + r] = ps3;
        }
        __syncthreads();

        #pragma unroll 2
        for (int j = 0; j < 64; ++j) {
            float4 p = *(const float4*)&Ps[j * PP + ty * 4];
            const float* kr = Ks + j * KP + tx;
            #pragma unroll
            for (int cc = 0; cc < 16; cc++) {
                float kv = kr[cc * 16];
                acc[0][cc] += p.x * kv;
                acc[1][cc] += p.y * kv;
                acc[2][cc] += p.z * kv;
                acc[3][cc] += p.w * kv;
            }
        }
    }

    #pragma unroll
    for (int r = 0; r < 4; r++) {
        int ig = q0 + ty * 4 + r;
        float inv = (ig > 0 && lr[r] > 0.f) ? (1.0f / lr[r]) : 0.f;
        float* crow = g_ctx + ((size_t)b * T_SEQ + ig) * D_DIM;
        #pragma unroll
        for (int cc = 0; cc < 16; cc++)
            crow[tx + 16 * cc] = acc[r][cc] * inv;
    }
}

// ---------------------------------------------------------------------------
// tf32 tensor-core GEMM skeleton shared by fc1/fc2.
// Block tile 128x128, 8 warps (2x4), warp tile 64x32, k-tile 32.
// A smem [128][36] (stride%32=4 -> conflict-free frag loads),
// B smem [32][136]  (stride%32=8 -> conflict-free frag loads).
// Elements converted to tf32 bits once, at smem-store time.
// ---------------------------------------------------------------------------
#define AS_LD 36
#define BS_LD 136

// FC1: h = relu([x | ctx] @ W1 + b1)   M=65536, K=512, N=1024
__global__ __launch_bounds__(256, 1)
void fc1_kernel(const float* __restrict__ x,
                const float* __restrict__ W1,
                const float* __restrict__ b1)
{
    __shared__ uint32_t As[128][AS_LD];
    __shared__ uint32_t Bs[32][BS_LD];

    const int bm = blockIdx.y * 128, bn = blockIdx.x * 128;
    const int tid  = threadIdx.x;
    const int warp = tid >> 5, lane = tid & 31;
    const int gid  = lane >> 2, tig = lane & 3;
    const int wm = (warp >> 2) * 64;      // 0 or 64
    const int wn = (warp & 3) * 32;       // 0..96

    float c[4][4][4];
    #pragma unroll
    for (int i = 0; i < 4; i++)
        #pragma unroll
        for (int j = 0; j < 4; j++)
            #pragma unroll
            for (int r = 0; r < 4; r++) c[i][j][r] = 0.f;

    float4 pa[4], pb[4];

    auto loadA = [&](int k0) {
        const float* base = (k0 < 256) ? (x + k0) : (g_ctx + (k0 - 256));
        #pragma unroll
        for (int r = 0; r < 4; r++) {
            int idx = tid + r * 256;          // 0..1023 float4
            int m = idx >> 3, kq = idx & 7;
            pa[r] = *(const float4*)(base + (size_t)(bm + m) * 256 + kq * 4);
        }
    };
    auto loadB = [&](int k0) {
        #pragma unroll
        for (int r = 0; r < 4; r++) {
            int idx = tid + r * 256;
            int kk = idx >> 5, n4 = idx & 31;
            pb[r] = *(const float4*)(W1 + (size_t)(k0 + kk) * 1024 + bn + n4 * 4);
        }
    };
    auto storeS = [&]() {
        #pragma unroll
        for (int r = 0; r < 4; r++) {
            int idx = tid + r * 256;
            int m = idx >> 3, kq = idx & 7;
            As[m][kq * 4 + 0] = f2tf(pa[r].x);
            As[m][kq * 4 + 1] = f2tf(pa[r].y);
            As[m][kq * 4 + 2] = f2tf(pa[r].z);
            As[m][kq * 4 + 3] = f2tf(pa[r].w);
        }
        #pragma unroll
        for (int r = 0; r < 4; r++) {
            int idx = tid + r * 256;
            int kk = idx >> 5, n4 = idx & 31;
            uint4 u;
            u.x = f2tf(pb[r].x); u.y = f2tf(pb[r].y);
            u.z = f2tf(pb[r].z); u.w = f2tf(pb[r].w);
            *(uint4*)&Bs[kk][n4 * 4] = u;
        }
    };

    loadA(0); loadB(0); storeS();
    int k0 = 0;
    while (true) {
        __syncthreads();
        int kn = k0 + 32;
        bool more = kn < 512;
        if (more) { loadA(kn); loadB(kn); }

        #pragma unroll
        for (int ks = 0; ks < 4; ks++) {
            const int kc = ks * 8;
            uint32_t a[4][4], bfr[4][2];
            #pragma unroll
            for (int mt = 0; mt < 4; mt++) {
                int rb = wm + mt * 16 + gid;
                a[mt][0] = As[rb][kc + tig];
                a[mt][1] = As[rb + 8][kc + tig];
                a[mt][2] = As[rb][kc + tig + 4];
                a[mt][3] = As[rb + 8][kc + tig + 4];
            }
            #pragma unroll
            for (int nt = 0; nt < 4; nt++) {
                int cb = wn + nt * 8 + gid;
                bfr[nt][0] = Bs[kc + tig][cb];
                bfr[nt][1] = Bs[kc + tig + 4][cb];
            }
            #pragma unroll
            for (int mt = 0; mt < 4; mt++)
                #pragma unroll
                for (int nt = 0; nt < 4; nt++)
                    mma_tf32(c[mt][nt][0], c[mt][nt][1], c[mt][nt][2], c[mt][nt][3],
                             a[mt][0], a[mt][1], a[mt][2], a[mt][3],
                             bfr[nt][0], bfr[nt][1]);
        }
        if (!more) break;
        __syncthreads();
        storeS();
        k0 = kn;
    }

    // Epilogue: bias + relu -> g_h
    #pragma unroll
    for (int nt = 0; nt < 4; nt++) {
        int col = bn + wn + nt * 8 + 2 * tig;
        float bb0 = b1[col], bb1 = b1[col + 1];
        #pragma unroll
        for (int mt = 0; mt < 4; mt++) {
            size_t r0 = (size_t)(bm + wm + mt * 16 + gid);
            size_t r1 = r0 + 8;
            float2 v0 = { fmaxf(c[mt][nt][0] + bb0, 0.f), fmaxf(c[mt][nt][1] + bb1, 0.f) };
            float2 v1 = { fmaxf(c[mt][nt][2] + bb0, 0.f), fmaxf(c[mt][nt][3] + bb1, 0.f) };
            *(float2*)(g_h + r0 * 1024 + col) = v0;
            *(float2*)(g_h + r1 * 1024 + col) = v1;
        }
    }
}

// FC2: out = h @ W2 + b2   M=65536, K=1024, N=512; split-halves store
__global__ __launch_bounds__(256, 1)
void fc2_kernel(const float* __restrict__ W2,
                const float* __restrict__ b2,
                float* __restrict__ out)
{
    __shared__ uint32_t As[128][AS_LD];
    __shared__ uint32_t Bs[32][BS_LD];

    const int bm = blockIdx.y * 128, bn = blockIdx.x * 128;
    const int tid  = threadIdx.x;
    const int warp = tid >> 5, lane = tid & 31;
    const int gid  = lane >> 2, tig = lane & 3;
    const int wm = (warp >> 2) * 64;
    const int wn = (warp & 3) * 32;

    float c[4][4][4];
    #pragma unroll
    for (int i = 0; i < 4; i++)
        #pragma unroll
        for (int j = 0; j < 4; j++)
            #pragma unroll
            for (int r = 0; r < 4; r++) c[i][j][r] = 0.f;

    float4 pa[4], pb[4];

    auto loadA = [&](int k0) {
        #pragma unroll
        for (int r = 0; r < 4; r++) {
            int idx = tid + r * 256;
            int m = idx >> 3, kq = idx & 7;
            pa[r] = *(const float4*)(g_h + (size_t)(bm + m) * 1024 + k0 + kq * 4);
        }
    };
    auto loadB = [&](int k0) {
        #pragma unroll
        for (int r = 0; r < 4; r++) {
            int idx = tid + r * 256;
            int kk = idx >> 5, n4 = idx & 31;
            pb[r] = *(const float4*)(W2 + (size_t)(k0 + kk) * 512 + bn + n4 * 4);
        }
    };
    auto storeS = [&]() {
        #pragma unroll
        for (int r = 0; r < 4; r++) {
            int idx = tid + r * 256;
            int m = idx >> 3, kq = idx & 7;
            As[m][kq * 4 + 0] = f2tf(pa[r].x);
            As[m][kq * 4 + 1] = f2tf(pa[r].y);
            As[m][kq * 4 + 2] = f2tf(pa[r].z);
            As[m][kq * 4 + 3] = f2tf(pa[r].w);
        }
        #pragma unroll
        for (int r = 0; r < 4; r++) {
            int idx = tid + r * 256;
            int kk = idx >> 5, n4 = idx & 31;
            uint4 u;
            u.x = f2tf(pb[r].x); u.y = f2tf(pb[r].y);
            u.z = f2tf(pb[r].z); u.w = f2tf(pb[r].w);
            *(uint4*)&Bs[kk][n4 * 4] = u;
        }
    };

    loadA(0); loadB(0); storeS();
    int k0 = 0;
    while (true) {
        __syncthreads();
        int kn = k0 + 32;
        bool more = kn < 1024;
        if (more) { loadA(kn); loadB(kn); }

        #pragma unroll
        for (int ks = 0; ks < 4; ks++) {
            const int kc = ks * 8;
            uint32_t a[4][4], bfr[4][2];
            #pragma unroll
            for (int mt = 0; mt < 4; mt++) {
                int rb = wm + mt * 16 + gid;
                a[mt][0] = As[rb][kc + tig];
                a[mt][1] = As[rb + 8][kc + tig];
                a[mt][2] = As[rb][kc + tig + 4];
                a[mt][3] = As[rb + 8][kc + tig + 4];
            }
            #pragma unroll
            for (int nt = 0; nt < 4; nt++) {
                int cb = wn + nt * 8 + gid;
                bfr[nt][0] = Bs[kc + tig][cb];
                bfr[nt][1] = Bs[kc + tig + 4][cb];
            }
            #pragma unroll
            for (int mt = 0; mt < 4; mt++)
                #pragma unroll
                for (int nt = 0; nt < 4; nt++)
                    mma_tf32(c[mt][nt][0], c[mt][nt][1], c[mt][nt][2], c[mt][nt][3],
                             a[mt][0], a[mt][1], a[mt][2], a[mt][3],
                             bfr[nt][0], bfr[nt][1]);
        }
        if (!more) break;
        __syncthreads();
        storeS();
        k0 = kn;
    }

    // Epilogue: bias + split-halves store
    #pragma unroll
    for (int nt = 0; nt < 4; nt++) {
        int n0 = bn + wn + nt * 8 + 2 * tig;
        float bb0 = b2[n0], bb1 = b2[n0 + 1];
        float* obase = (n0 < 256) ? (out + n0) : (out + HALF_OFF + (n0 - 256));
        #pragma unroll
        for (int mt = 0; mt < 4; mt++) {
            size_t r0 = (size_t)(bm + wm + mt * 16 + gid);
            size_t r1 = r0 + 8;
            float2 v0 = { c[mt][nt][0] + bb0, c[mt][nt][1] + bb1 };
            float2 v1 = { c[mt][nt][2] + bb0, c[mt][nt][3] + bb1 };
            *(float2*)(obase + r0 * 256) = v0;
            *(float2*)(obase + r1 * 256) = v1;
        }
    }
}

// ---------------------------------------------------------------------------
extern "C" void kernel_launch(void* const* d_in, const int* in_sizes, int n_in,
                              void* d_out, int out_size)
{
    const float* x  = (const float*)d_in[0];
    const float* W1 = (const float*)d_in[1];
    const float* b1 = (const float*)d_in[2];
    const float* W2 = (const float*)d_in[3];
    const float* b2 = (const float*)d_in[4];
    float* out = (float*)d_out;

    cudaFuncSetAttribute(attn_kernel,
                         cudaFuncAttributeMaxDynamicSharedMemorySize, ATTN_SMEM);

    attn_kernel<<<dim3(32, B_BATCH), 256, ATTN_SMEM>>>(x);
    fc1_kernel<<<dim3(8, 512), 256>>>(x, W1, b1);
    fc2_kernel<<<dim3(4, 512), 256>>>(W2, b2, out);
}